// round 1
// baseline (speedup 1.0000x reference)
#include <cuda_runtime.h>
#include <math.h>

#define BATCH 262144
#define HIDDEN 512
#define NDIM 12
#define TRI 78           // N*(N+1)/2
#define OUTC (TRI + 1)   // 79

// Static scratch (no allocations allowed in kernel_launch)
__device__ float g_h1[(size_t)BATCH * HIDDEN];   // 512 MB
__device__ float g_h2[(size_t)BATCH * HIDDEN];   // 512 MB
__device__ float g_o [(size_t)BATCH * OUTC];     // ~83 MB

// ---------------------------------------------------------------------------
// Tiled SGEMM with fused bias + activation.
// C[M,N] = act(A[M,K] @ W[K,N] + bias[N])
// ACT: 1 = relu, 2 = softplus
// BM=BN=128, BK=16, 256 threads, 8x8 per-thread micro-tile.
// M must be a multiple of 128 (true here: 262144). N,K arbitrary (guarded).
// ---------------------------------------------------------------------------
template <int ACT>
__global__ __launch_bounds__(256) void sgemm_act(
    const float* __restrict__ A, const float* __restrict__ W,
    const float* __restrict__ bias, float* __restrict__ C,
    int M, int N, int K)
{
    constexpr int BM = 128, BN = 128, BK = 16;
    __shared__ float As[BK][BM];
    __shared__ float Bs[BK][BN];

    const int tid = threadIdx.x;
    const int m0 = blockIdx.y * BM;
    const int n0 = blockIdx.x * BN;
    const int ty = tid >> 4;   // 0..15
    const int tx = tid & 15;   // 0..15

    // A-tile load map: 128 rows x 16 k; thread -> 8 contiguous k-floats
    const int aRow = tid >> 1;
    const int aK   = (tid & 1) * 8;
    // B-tile load map: 16 k-rows x 128 n; thread -> 8 contiguous n-floats
    const int bK   = tid >> 4;
    const int bCol = (tid & 15) * 8;

    const bool fullN = (n0 + BN <= N);

    float acc[8][8];
#pragma unroll
    for (int i = 0; i < 8; i++)
#pragma unroll
        for (int j = 0; j < 8; j++) acc[i][j] = 0.f;

    for (int kt = 0; kt < K; kt += BK) {
        const bool fullK = (kt + BK <= K);

        // ---- load A tile (transposed into smem) ----
        if (fullK) {
            const float* ap = A + (size_t)(m0 + aRow) * K + kt + aK;
            float4 a0 = *(const float4*)(ap);
            float4 a1 = *(const float4*)(ap + 4);
            As[aK + 0][aRow] = a0.x; As[aK + 1][aRow] = a0.y;
            As[aK + 2][aRow] = a0.z; As[aK + 3][aRow] = a0.w;
            As[aK + 4][aRow] = a1.x; As[aK + 5][aRow] = a1.y;
            As[aK + 6][aRow] = a1.z; As[aK + 7][aRow] = a1.w;
        } else {
#pragma unroll
            for (int u = 0; u < 8; u++) {
                int k = kt + aK + u;
                As[aK + u][aRow] =
                    (k < K) ? A[(size_t)(m0 + aRow) * K + k] : 0.f;
            }
        }

        // ---- load B tile ----
        if (fullK && fullN) {
            const float* wp = W + (size_t)(kt + bK) * N + n0 + bCol;
            float4 b0 = *(const float4*)(wp);
            float4 b1 = *(const float4*)(wp + 4);
            *(float4*)&Bs[bK][bCol]     = b0;
            *(float4*)&Bs[bK][bCol + 4] = b1;
        } else {
#pragma unroll
            for (int u = 0; u < 8; u++) {
                int k = kt + bK;
                int n = n0 + bCol + u;
                Bs[bK][bCol + u] =
                    (k < K && n < N) ? W[(size_t)k * N + n] : 0.f;
            }
        }

        __syncthreads();

#pragma unroll
        for (int k = 0; k < BK; k++) {
            float a[8], b[8];
#pragma unroll
            for (int i = 0; i < 8; i++) a[i] = As[k][ty * 8 + i];
#pragma unroll
            for (int j = 0; j < 8; j++) b[j] = Bs[k][tx * 8 + j];
#pragma unroll
            for (int i = 0; i < 8; i++)
#pragma unroll
                for (int j = 0; j < 8; j++)
                    acc[i][j] = fmaf(a[i], b[j], acc[i][j]);
        }
        __syncthreads();
    }

    // ---- epilogue: bias + activation + store ----
#pragma unroll
    for (int i = 0; i < 8; i++) {
        const int row = m0 + ty * 8 + i;
#pragma unroll
        for (int j = 0; j < 8; j++) {
            const int col = n0 + tx * 8 + j;
            if (col < N) {
                float v = acc[i][j] + bias[col];
                if (ACT == 1) {
                    v = fmaxf(v, 0.f);
                } else if (ACT == 2) {
                    v = (v > 20.f) ? v : log1pf(expf(v));
                }
                C[(size_t)row * N + col] = v;
            }
        }
    }
}

// ---------------------------------------------------------------------------
// MMT epilogue: per batch row, scatter softplus outputs into lower-tri L
// and compute MMT[i][k] = sum_{j<=min(i,k)} L[i][j]*L[k][j]; emit c.
// Output layout: dst[0 .. B*144) = MMT flattened, dst[B*144 .. B*145) = c.
// 16 rows per block, 256 threads.
// ---------------------------------------------------------------------------
__global__ __launch_bounds__(256) void mmt_kernel(
    const float* __restrict__ o, float* __restrict__ dst)
{
    __shared__ float s[16][OUTC];
    const int b0 = blockIdx.x * 16;
    const int tid = threadIdx.x;

    for (int i = tid; i < 16 * OUTC; i += 256) {
        int r = i / OUTC, c = i - r * OUTC;
        s[r][c] = o[(size_t)(b0 + r) * OUTC + c];
    }
    __syncthreads();

    for (int i = tid; i < 16 * 144; i += 256) {
        int r = i / 144;
        int e = i - r * 144;
        int ii = e / NDIM;
        int kk = e - ii * NDIM;
        int mn = ii < kk ? ii : kk;
        const float* Li = &s[r][ii * (ii + 1) / 2];
        const float* Lk = &s[r][kk * (kk + 1) / 2];
        float acc = 0.f;
#pragma unroll 4
        for (int j = 0; j <= mn; j++) acc = fmaf(Li[j], Lk[j], acc);
        dst[(size_t)(b0 + r) * 144 + e] = acc;
    }

    if (tid < 16)
        dst[(size_t)BATCH * 144 + b0 + tid] = s[tid][TRI];
}

// ---------------------------------------------------------------------------
extern "C" void kernel_launch(void* const* d_in, const int* in_sizes, int n_in,
                              void* d_out, int out_size)
{
    const float* x  = (const float*)d_in[0];
    const float* W1 = (const float*)d_in[1];
    const float* b1 = (const float*)d_in[2];
    const float* W2 = (const float*)d_in[3];
    const float* b2 = (const float*)d_in[4];
    const float* W3 = (const float*)d_in[5];
    const float* b3 = (const float*)d_in[6];
    float* out = (float*)d_out;

    float *h1, *h2, *oo;
    cudaGetSymbolAddress((void**)&h1, g_h1);
    cudaGetSymbolAddress((void**)&h2, g_h2);
    cudaGetSymbolAddress((void**)&oo, g_o);

    dim3 gridHid(HIDDEN / 128, BATCH / 128);   // (4, 2048)
    dim3 gridOut(1, BATCH / 128);              // 79 cols fit in one 128 tile

    // Layer 1: h1 = relu(x @ W1 + b1)   [K=12]
    sgemm_act<1><<<gridHid, 256>>>(x, W1, b1, h1, BATCH, HIDDEN, NDIM);
    // Layer 2: h2 = relu(h1 @ W2 + b2)  [K=512] — dominant GEMM
    sgemm_act<1><<<gridHid, 256>>>(h1, W2, b2, h2, BATCH, HIDDEN, HIDDEN);
    // Layer 3: o = softplus(h2 @ W3 + b3) [N=79]
    sgemm_act<2><<<gridOut, 256>>>(h2, W3, b3, oo, BATCH, OUTC, HIDDEN);
    // Epilogue: L scatter + L@L^T + c
    mmt_kernel<<<BATCH / 16, 256>>>(oo, out);
}

// round 3
// speedup vs baseline: 3.3956x; 3.3956x over previous
#include <cuda_runtime.h>
#include <cuda_bf16.h>
#include <math.h>
#include <stdint.h>

#define BATCH 262144
#define HID 512
#define NDIM 12
#define TRI 78
#define OUTC 79

typedef __nv_bfloat16 bf16;
typedef __nv_bfloat162 bf162;

// Packed operand layout: row-major, width 1024 bf16 per row.
// col offset for k: (k/32)*64 + (k%32)  -> hi plane;  +32 -> lo plane.
__device__ bf16 g_h1pk[(size_t)BATCH * 1024];   // 512 MB
__device__ bf16 g_h2pk[(size_t)BATCH * 1024];   // 512 MB
__device__ bf16 g_w2pk[(size_t)HID * 1024];     // 1 MB   (rows = out-col n)
__device__ bf16 g_w3pk[(size_t)128 * 1024];     // 256 KB (rows n, zero-pad >=79)

#define SWZ(o) ((o) ^ (((o) >> 3) & 0x70))

__device__ __forceinline__ uint32_t smem_u32(const void* p) {
    uint32_t a;
    asm("{ .reg .u64 t; cvta.to.shared.u64 t, %1; cvt.u32.u64 %0, t; }"
        : "=r"(a) : "l"(p));
    return a;
}
__device__ __forceinline__ void cp16(uint32_t dst, const void* src) {
    asm volatile("cp.async.cg.shared.global [%0], [%1], 16;"
                 :: "r"(dst), "l"(src));
}
#define CP_COMMIT() asm volatile("cp.async.commit_group;" ::: "memory")
#define CP_WAIT0()  asm volatile("cp.async.wait_group 0;" ::: "memory")

#define LDSM_X4(r0, r1, r2, r3, a)                                            \
    asm volatile("ldmatrix.sync.aligned.m8n8.x4.shared.b16 {%0,%1,%2,%3}, [%4];" \
                 : "=r"(r0), "=r"(r1), "=r"(r2), "=r"(r3) : "r"(a))
#define LDSM_X2(r0, r1, a)                                                    \
    asm volatile("ldmatrix.sync.aligned.m8n8.x2.shared.b16 {%0,%1}, [%2];"    \
                 : "=r"(r0), "=r"(r1) : "r"(a))
#define MMA_BF16(c, a, b)                                                     \
    asm volatile("mma.sync.aligned.m16n8k16.row.col.f32.bf16.bf16.f32 "       \
                 "{%0,%1,%2,%3}, {%4,%5,%6,%7}, {%8,%9}, {%0,%1,%2,%3};"      \
                 : "+f"((c)[0]), "+f"((c)[1]), "+f"((c)[2]), "+f"((c)[3])     \
                 : "r"((a)[0]), "r"((a)[1]), "r"((a)[2]), "r"((a)[3]),        \
                   "r"((b)[0]), "r"((b)[1]))

static __device__ __forceinline__ float softplusf(float v) {
    return (v > 20.f) ? v : log1pf(expf(v));
}
static __device__ __forceinline__ int pkoff(int k) {
    return ((k >> 5) << 6) + (k & 31);
}

// ---------------- weight converters (transpose + hi/lo split + pack) --------
__global__ __launch_bounds__(256) void conv_w2(const float* __restrict__ W2) {
    int t = blockIdx.x * 256 + threadIdx.x;        // < 512*512
    int n = t >> 9, k = t & 511;
    float v = W2[(size_t)k * HID + n];
    bf16 h = __float2bfloat16(v);
    size_t o = (size_t)n * 1024 + pkoff(k);
    g_w2pk[o] = h;
    g_w2pk[o + 32] = __float2bfloat16(v - __bfloat162float(h));
}
__global__ __launch_bounds__(256) void conv_w3(const float* __restrict__ W3) {
    int t = blockIdx.x * 256 + threadIdx.x;        // < 128*512
    int n = t >> 9, k = t & 511;
    float v = (n < OUTC) ? W3[(size_t)k * OUTC + n] : 0.f;
    bf16 h = __float2bfloat16(v);
    size_t o = (size_t)n * 1024 + pkoff(k);
    g_w3pk[o] = h;
    g_w3pk[o + 32] = __float2bfloat16(v - __bfloat162float(h));
}

// ---------------- layer 1 (K=12, memory-bound FFMA) -------------------------
__global__ __launch_bounds__(256) void l1_kernel(
    const float* __restrict__ x, const float* __restrict__ W1,
    const float* __restrict__ b1, bf16* __restrict__ hpk)
{
    __shared__ float W1s[NDIM][HID];
    __shared__ float b1s[HID];
    __shared__ float xs[32][NDIM];
    const int tid = threadIdx.x;
    const int b0 = blockIdx.x * 32;

    for (int i = tid; i < NDIM * HID; i += 256) W1s[i / HID][i % HID] = W1[i];
    for (int i = tid; i < HID; i += 256) b1s[i] = b1[i];
    for (int i = tid; i < 32 * NDIM; i += 256)
        xs[i / NDIM][i % NDIM] = x[(size_t)b0 * NDIM + i];
    __syncthreads();

    for (int it = 0; it < 32; ++it) {
        int p = tid + it * 256;
        int r = p >> 8;
        int c = (p & 255) * 2;
        float a0 = b1s[c], a1 = b1s[c + 1];
#pragma unroll
        for (int k = 0; k < NDIM; ++k) {
            float xv = xs[r][k];
            a0 = fmaf(xv, W1s[k][c], a0);
            a1 = fmaf(xv, W1s[k][c + 1], a1);
        }
        a0 = fmaxf(a0, 0.f); a1 = fmaxf(a1, 0.f);
        bf16 h0 = __float2bfloat16(a0), h1 = __float2bfloat16(a1);
        bf16 l0 = __float2bfloat16(a0 - __bfloat162float(h0));
        bf16 l1 = __float2bfloat16(a1 - __bfloat162float(h1));
        size_t base = (size_t)(b0 + r) * 1024 + pkoff(c);
        *(bf162*)(hpk + base)      = __halves2bfloat162(h0, h1);
        *(bf162*)(hpk + base + 32) = __halves2bfloat162(l0, l1);
    }
}

// ---------------- mma.sync bf16 3-term-split GEMM ---------------------------
// C[128m,128n] = act(A @ B^T + bias). A rows from Apk (m0+..), B rows (n0+..).
// ACT=1: relu -> packed hi/lo write to Opk.   ACT=2: softplus + L@L^T -> dst.
template <int ACT>
__global__ __launch_bounds__(256, 2) void mma_gemm(
    const bf16* __restrict__ Apk, const bf16* __restrict__ Bpk,
    const float* __restrict__ bias,
    bf16* __restrict__ Opk, float* __restrict__ dst)
{
    extern __shared__ char smem[];
    const uint32_t sb = smem_u32(smem);
    const int tid = threadIdx.x;
    const int lane = tid & 31;
    const int wid = tid >> 5;
    const int wm = wid >> 2;        // 0..1  (m band of 64)
    const int wn = wid & 3;         // 0..3  (n band of 32)
    const int m0 = blockIdx.y * 128;
    const int n0 = blockIdx.x * 128;

    float acc[4][4][4];
#pragma unroll
    for (int i = 0; i < 4; i++)
#pragma unroll
        for (int j = 0; j < 4; j++)
#pragma unroll
            for (int k = 0; k < 4; k++) acc[i][j][k] = 0.f;

    const bf16* Abase = Apk + (size_t)m0 * 1024;
    const bf16* Bbase = Bpk + (size_t)n0 * 1024;

    auto load_chunk = [&](int c, int buf) {
        uint32_t ab = sb + (buf ? 16384 : 0);
        uint32_t bb = sb + 32768 + (buf ? 16384 : 0);
        const bf16* As = Abase + c * 64;
        const bf16* Bs = Bbase + c * 64;
#pragma unroll
        for (int it = 0; it < 8; ++it) {
            int u = tid + it * 256;              // 0..2047
            int half = u >> 10;
            int v = u & 1023;
            int r = v >> 3, q = v & 7;
            const bf16* s = (half ? Bs : As) + (size_t)r * 1024 + q * 8;
            uint32_t d = (half ? bb : ab) + SWZ(r * 128 + q * 16);
            cp16(d, s);
        }
        CP_COMMIT();
    };

    load_chunk(0, 0);

    for (int c = 0; c < 16; ++c) {
        CP_WAIT0();
        __syncthreads();
        if (c < 15) load_chunk(c + 1, (c + 1) & 1);

        const int buf = c & 1;
        const uint32_t ab = sb + (buf ? 16384 : 0);
        const uint32_t bb = sb + 32768 + (buf ? 16384 : 0);

#pragma unroll
        for (int ks = 0; ks < 2; ++ks) {
            uint32_t bfr[2][4][2];
            const int brow0 = wn * 32 + (lane & 7);
            const int bsel = (lane >> 3) & 1;
#pragma unroll
            for (int pl = 0; pl < 2; ++pl)
#pragma unroll
                for (int nt = 0; nt < 4; ++nt) {
                    int row = brow0 + nt * 8;
                    int seg = pl * 4 + ks * 2 + bsel;
                    uint32_t ad = bb + row * 128 + ((seg ^ (row & 7)) << 4);
                    LDSM_X2(bfr[pl][nt][0], bfr[pl][nt][1], ad);
                }
#pragma unroll
            for (int mt = 0; mt < 4; ++mt) {
                uint32_t afr[2][4];
                const int arow = wm * 64 + mt * 16 + (lane & 15);
                const int asel = lane >> 4;
#pragma unroll
                for (int pl = 0; pl < 2; ++pl) {
                    int seg = pl * 4 + ks * 2 + asel;
                    uint32_t ad = ab + arow * 128 + ((seg ^ (arow & 7)) << 4);
                    LDSM_X4(afr[pl][0], afr[pl][1], afr[pl][2], afr[pl][3], ad);
                }
#pragma unroll
                for (int nt = 0; nt < 4; ++nt)
                    MMA_BF16(acc[mt][nt], afr[0], bfr[0][nt]);   // hi*hi
#pragma unroll
                for (int nt = 0; nt < 4; ++nt)
                    MMA_BF16(acc[mt][nt], afr[0], bfr[1][nt]);   // hi*lo
#pragma unroll
                for (int nt = 0; nt < 4; ++nt)
                    MMA_BF16(acc[mt][nt], afr[1], bfr[0][nt]);   // lo*hi
            }
        }
        __syncthreads();
    }

    // ---------------- epilogue ----------------
    const int r0 = wm * 64 + (lane >> 2);
    const int c0 = wn * 32 + (lane & 3) * 2;

    if (ACT == 1) {
#pragma unroll
        for (int mt = 0; mt < 4; ++mt)
#pragma unroll
            for (int nt = 0; nt < 4; ++nt) {
                const int gc = n0 + c0 + nt * 8;
                const float bb0 = __ldg(bias + gc);
                const float bb1 = __ldg(bias + gc + 1);
#pragma unroll
                for (int h = 0; h < 2; ++h) {
                    const int row = m0 + r0 + mt * 16 + 8 * h;
                    float v0 = fmaxf(acc[mt][nt][2 * h] + bb0, 0.f);
                    float v1 = fmaxf(acc[mt][nt][2 * h + 1] + bb1, 0.f);
                    bf16 h0 = __float2bfloat16(v0), h1 = __float2bfloat16(v1);
                    bf16 l0 = __float2bfloat16(v0 - __bfloat162float(h0));
                    bf16 l1 = __float2bfloat16(v1 - __bfloat162float(h1));
                    size_t off = (size_t)row * 1024 + pkoff(gc);
                    *(bf162*)(Opk + off)      = __halves2bfloat162(h0, h1);
                    *(bf162*)(Opk + off + 32) = __halves2bfloat162(l0, l1);
                }
            }
    } else {
        float* stage = (float*)smem;          // 128 x 81 floats (reuse bufs)
#pragma unroll
        for (int mt = 0; mt < 4; ++mt)
#pragma unroll
            for (int nt = 0; nt < 4; ++nt) {
                const int col = c0 + nt * 8;
                if (col >= 80) continue;
#pragma unroll
                for (int h = 0; h < 2; ++h) {
                    const int row = r0 + mt * 16 + 8 * h;
                    if (col < OUTC)
                        stage[row * 81 + col] =
                            softplusf(acc[mt][nt][2 * h] + __ldg(bias + col));
                    if (col + 1 < OUTC)
                        stage[row * 81 + col + 1] =
                            softplusf(acc[mt][nt][2 * h + 1] + __ldg(bias + col + 1));
                }
            }
        __syncthreads();

        for (int i = tid; i < 128 * 144; i += 256) {
            int r = i / 144;
            int e = i - r * 144;
            int ii = e / 12;
            int kk = e - ii * 12;
            int mn = ii < kk ? ii : kk;
            const float* Li = stage + r * 81 + ((ii * (ii + 1)) >> 1);
            const float* Lk = stage + r * 81 + ((kk * (kk + 1)) >> 1);
            float a = 0.f;
#pragma unroll 4
            for (int j = 0; j <= mn; ++j) a = fmaf(Li[j], Lk[j], a);
            dst[(size_t)m0 * 144 + i] = a;
        }
        if (tid < 128)
            dst[(size_t)BATCH * 144 + m0 + tid] = stage[tid * 81 + TRI];
    }
}

// ---------------- launch ----------------------------------------------------
extern "C" void kernel_launch(void* const* d_in, const int* in_sizes, int n_in,
                              void* d_out, int out_size)
{
    const float* x  = (const float*)d_in[0];
    const float* W1 = (const float*)d_in[1];
    const float* b1 = (const float*)d_in[2];
    const float* W2 = (const float*)d_in[3];
    const float* b2 = (const float*)d_in[4];
    const float* W3 = (const float*)d_in[5];
    const float* b3 = (const float*)d_in[6];
    float* out = (float*)d_out;

    bf16 *h1pk, *h2pk, *w2pk, *w3pk;
    cudaGetSymbolAddress((void**)&h1pk, g_h1pk);
    cudaGetSymbolAddress((void**)&h2pk, g_h2pk);
    cudaGetSymbolAddress((void**)&w2pk, g_w2pk);
    cudaGetSymbolAddress((void**)&w3pk, g_w3pk);

    conv_w2<<<(HID * HID) / 256, 256>>>(W2);
    conv_w3<<<(128 * HID) / 256, 256>>>(W3);
    l1_kernel<<<BATCH / 32, 256>>>(x, W1, b1, h1pk);

    constexpr int SMEM = 65536;
    cudaFuncSetAttribute(mma_gemm<1>,
                         cudaFuncAttributeMaxDynamicSharedMemorySize, SMEM);
    cudaFuncSetAttribute(mma_gemm<2>,
                         cudaFuncAttributeMaxDynamicSharedMemorySize, SMEM);

    // Layer 2: h2 = relu(h1 @ W2 + b2)
    mma_gemm<1><<<dim3(4, BATCH / 128), 256, SMEM>>>(h1pk, w2pk, b2, h2pk, nullptr);
    // Layer 3 fused: softplus + L@L^T + c
    mma_gemm<2><<<dim3(1, BATCH / 128), 256, SMEM>>>(h2pk, w3pk, b3, nullptr, out);
}